// round 7
// baseline (speedup 1.0000x reference)
#include <cuda_runtime.h>
#include <cuda_fp16.h>
#include <cstdint>

// ============================ problem sizes ============================
#define M_TOT 8192      // B*S = 4*2048
#define DI    4096
#define DO    4096
#define CAPM  1024

// ============================ device scratch ===========================
__device__ __half g_x16[(size_t)M_TOT * DI];   // 64 MB fp16 activations
__device__ __half g_w16[(size_t)DO * DI];      // 32 MB fp16 dequantized weights
__device__ float  g_scores[CAPM];
__device__ float  g_attn[CAPM];
__device__ float  g_memout[DO];

// ============================ PTX helpers ==============================
__device__ __forceinline__ uint32_t smem_u32(const void* p) {
    uint32_t a;
    asm("{ .reg .u64 t; cvta.to.shared.u64 t, %1; cvt.u32.u64 %0, t; }"
        : "=r"(a) : "l"(p));
    return a;
}

#define SWZ128(off) ((off) ^ (((off) >> 3) & 0x70))

#define CP16(dst, src) \
    asm volatile("cp.async.cg.shared.global [%0], [%1], 16;\n" \
                 :: "r"(dst), "l"(src) : "memory")
#define CP_COMMIT() asm volatile("cp.async.commit_group;\n" ::: "memory")
#define CP_WAIT(n)  asm volatile("cp.async.wait_group %0;\n" :: "n"(n) : "memory")

#define LDSM4(r0, r1, r2, r3, addr) \
    asm volatile("ldmatrix.sync.aligned.m8n8.x4.shared.b16 {%0,%1,%2,%3}, [%4];" \
                 : "=r"(r0), "=r"(r1), "=r"(r2), "=r"(r3) : "r"(addr))

#define MMA16816(c, a, b) \
    asm volatile("mma.sync.aligned.m16n8k16.row.col.f32.f16.f16.f32 " \
                 "{%0,%1,%2,%3}, {%4,%5,%6,%7}, {%8,%9}, {%0,%1,%2,%3};" \
                 : "+f"((c)[0]), "+f"((c)[1]), "+f"((c)[2]), "+f"((c)[3]) \
                 : "r"((a)[0]), "r"((a)[1]), "r"((a)[2]), "r"((a)[3]), \
                   "r"((b)[0]), "r"((b)[1]))

// ============================ prep kernels =============================
__global__ void k_convert_x(const float* __restrict__ x) {
    int i = blockIdx.x * blockDim.x + threadIdx.x;          // float4 index
    const int n4 = (M_TOT * DI) / 4;
    if (i < n4) {
        float4 v = reinterpret_cast<const float4*>(x)[i];
        __half2 a = __floats2half2_rn(v.x, v.y);
        __half2 b = __floats2half2_rn(v.z, v.w);
        reinterpret_cast<__half2*>(g_x16)[2 * i]     = a;
        reinterpret_cast<__half2*>(g_x16)[2 * i + 1] = b;
    }
}

__global__ void k_convert_w(const float* __restrict__ wl, const float* __restrict__ ws) {
    int i = blockIdx.x * blockDim.x + threadIdx.x;          // float4 index
    const int n4 = (DO * DI) / 4;
    if (i < n4) {
        float4 v = reinterpret_cast<const float4*>(wl)[i];
        float s = ws[i >> 10];                              // row = i*4/4096
        __half2 a = __floats2half2_rn(v.x * s, v.y * s);
        __half2 b = __floats2half2_rn(v.z * s, v.w * s);
        reinterpret_cast<__half2*>(g_w16)[2 * i]     = a;
        reinterpret_cast<__half2*>(g_w16)[2 * i + 1] = b;
    }
}

// ======================= associative memory path =======================
__global__ void k_scores(const float* __restrict__ keys, const float* __restrict__ x) {
    int j = blockIdx.x;
    int t = threadIdx.x;
    const float4* kr = reinterpret_cast<const float4*>(keys + (size_t)j * DI);
    const float4* xr = reinterpret_cast<const float4*>(x);
    float acc = 0.f;
    #pragma unroll
    for (int i = t; i < DI / 4; i += 128) {
        float4 a = kr[i], b = xr[i];
        acc += a.x * b.x + a.y * b.y + a.z * b.z + a.w * b.w;
    }
    #pragma unroll
    for (int o = 16; o > 0; o >>= 1) acc += __shfl_xor_sync(0xFFFFFFFFu, acc, o);
    __shared__ float red[4];
    if ((t & 31) == 0) red[t >> 5] = acc;
    __syncthreads();
    if (t == 0) g_scores[j] = red[0] + red[1] + red[2] + red[3];
}

__global__ void k_softmax() {
    __shared__ float red[32];
    __shared__ float bcast;
    int t = threadIdx.x;                                    // 1024 threads
    float v = g_scores[t];
    float m = v;
    #pragma unroll
    for (int o = 16; o > 0; o >>= 1) m = fmaxf(m, __shfl_xor_sync(0xFFFFFFFFu, m, o));
    if ((t & 31) == 0) red[t >> 5] = m;
    __syncthreads();
    if (t < 32) {
        float mm = red[t];
        #pragma unroll
        for (int o = 16; o > 0; o >>= 1) mm = fmaxf(mm, __shfl_xor_sync(0xFFFFFFFFu, mm, o));
        if (t == 0) bcast = mm;
    }
    __syncthreads();
    float e = expf(v - bcast);
    float s = e;
    #pragma unroll
    for (int o = 16; o > 0; o >>= 1) s += __shfl_xor_sync(0xFFFFFFFFu, s, o);
    __syncthreads();
    if ((t & 31) == 0) red[t >> 5] = s;
    __syncthreads();
    if (t < 32) {
        float ss = red[t];
        #pragma unroll
        for (int o = 16; o > 0; o >>= 1) ss += __shfl_xor_sync(0xFFFFFFFFu, ss, o);
        if (t == 0) bcast = ss;
    }
    __syncthreads();
    g_attn[t] = e / bcast;
}

__global__ void k_memout(const float* __restrict__ vals) {
    __shared__ float a[CAPM];
    for (int i = threadIdx.x; i < CAPM; i += 128) a[i] = g_attn[i];
    __syncthreads();
    int o = blockIdx.x * 128 + threadIdx.x;                 // 32 blocks * 128
    float acc = 0.f;
    #pragma unroll 4
    for (int j = 0; j < CAPM; j++) acc += a[j] * vals[(size_t)j * DO + o];
    g_memout[o] = acc;
}

// post-pass: out += 0.01 * memory_out (broadcast over rows)
__global__ void k_addmem(float* __restrict__ out) {
    int i = blockIdx.x * blockDim.x + threadIdx.x;          // float4 index
    const int n4 = (M_TOT * DO) / 4;
    if (i < n4) {
        int col4 = (i & (DO / 4 - 1));
        float4 mo = reinterpret_cast<const float4*>(g_memout)[col4];
        float4 v  = reinterpret_cast<float4*>(out)[i];
        v.x += 0.01f * mo.x;
        v.y += 0.01f * mo.y;
        v.z += 0.01f * mo.z;
        v.w += 0.01f * mo.w;
        reinterpret_cast<float4*>(out)[i] = v;
    }
}

// ============================ main GEMM ================================
// Legacy-tensor-core path (mma.sync / HMMA.16816) — tcgen05 unavailable under
// the harness's plain sm_103 PTX target.
// CTA tile M=128, N=256, K-chunk=64. 256 threads = 8 warps (2x4), warp 64x64.
// 4-stage cp.async pipeline (48 KB/stage = 192 KB smem), wait_group(2).
// Inner loop: double-buffered ldmatrix fragments; swizzle applied to the FULL
// offset (base + ks*32) — adding ks*32 after swizzling carries into the row
// bits (the round-5 illegal-access bug).
#define STAGES      4
#define NKI         64            // 4096 / 64
#define STAGE_BYTES 49152
#define GEMM_SMEM   (STAGES * STAGE_BYTES)   // 196608

__device__ __forceinline__ void load_stage(uint32_t sb, int s, int kk,
                                           const __half* A, const __half* B,
                                           int tid) {
    uint32_t st = sb + s * STAGE_BYTES;
    size_t ko = (size_t)kk * 64;
    // A: 128 rows x 128 B; each thread does 4x 16B (row = tid/2, half-row tid%2)
    int ra = tid >> 1;
    int ca = (tid & 1) * 4;
    const char* ga = (const char*)(A + (size_t)ra * DI + ko) + ca * 16;
    #pragma unroll
    for (int c = 0; c < 4; c++) {
        uint32_t off = (uint32_t)(ra * 128 + (ca + c) * 16);
        CP16(st + SWZ128(off), ga + c * 16);
    }
    // B: 256 rows x 128 B; each thread does its own row (8x 16B)
    uint32_t bt = st + 16384;
    const char* gb = (const char*)(B + (size_t)tid * DI + ko);
    #pragma unroll
    for (int c = 0; c < 8; c++) {
        uint32_t off = (uint32_t)(tid * 128 + c * 16);
        CP16(bt + SWZ128(off), gb + c * 16);
    }
}

__global__ void __launch_bounds__(256, 1)
k_gemm(float* __restrict__ out) {
    extern __shared__ char smem[];
    uint32_t sb = smem_u32(smem);
    const int tid = threadIdx.x;
    const int wid = tid >> 5;
    const int lid = tid & 31;
    const int wm = wid & 1;          // 0..1  (M dimension)
    const int wn = wid >> 1;         // 0..3  (N dimension)

    // n varies fastest across blockIdx -> each wave keeps all of W in L2
    const size_t n0 = (size_t)(blockIdx.x & 15) * 256;   // 16 N tiles
    const size_t m0 = (size_t)(blockIdx.x >> 4) * 128;   // 64 M tiles
    const __half* Abase = g_x16 + m0 * DI;
    const __half* Bbase = g_w16 + n0 * DI;

    float acc[4][8][4];
    #pragma unroll
    for (int mt = 0; mt < 4; mt++)
        #pragma unroll
        for (int nt = 0; nt < 8; nt++)
            #pragma unroll
            for (int q = 0; q < 4; q++) acc[mt][nt][q] = 0.f;

    // per-lane UNSWIZZLED base offsets; swizzle applied at use on full offset
    const uint32_t a_row  = (uint32_t)(wm * 64 + (lid & 15));
    const uint32_t a_colb = (uint32_t)((lid >> 4) * 16);
    const uint32_t b_row  = (uint32_t)(wn * 64 + (lid & 7) + ((lid >> 4) << 3));
    const uint32_t b_colb = (uint32_t)(((lid >> 3) & 1) * 16);

    uint32_t a_base[4], b_base[4];
    #pragma unroll
    for (int mt = 0; mt < 4; mt++)
        a_base[mt] = (a_row + mt * 16) * 128 + a_colb;
    #pragma unroll
    for (int np = 0; np < 4; np++)
        b_base[np] = (b_row + np * 16) * 128 + b_colb;

    // prologue: fill 3 of 4 stages
    load_stage(sb, 0, 0, Abase, Bbase, tid); CP_COMMIT();
    load_stage(sb, 1, 1, Abase, Bbase, tid); CP_COMMIT();
    load_stage(sb, 2, 2, Abase, Bbase, tid); CP_COMMIT();

    uint32_t afr[2][4][4];
    uint32_t bfr[2][8][2];

    for (int k = 0; k < NKI; k++) {
        CP_WAIT(2);                       // data for iter k landed
        __syncthreads();

        int kn = k + 3;
        if (kn < NKI) load_stage(sb, kn & (STAGES - 1), kn, Abase, Bbase, tid);
        CP_COMMIT();

        uint32_t st = sb + (k & (STAGES - 1)) * STAGE_BYTES;
        uint32_t bt = st + 16384;

        // prefetch fragments for ks=0
        #pragma unroll
        for (int mt = 0; mt < 4; mt++)
            LDSM4(afr[0][mt][0], afr[0][mt][1], afr[0][mt][2], afr[0][mt][3],
                  st + SWZ128(a_base[mt]));
        #pragma unroll
        for (int np = 0; np < 4; np++)
            LDSM4(bfr[0][2 * np][0], bfr[0][2 * np][1],
                  bfr[0][2 * np + 1][0], bfr[0][2 * np + 1][1],
                  bt + SWZ128(b_base[np]));

        #pragma unroll
        for (int ks = 0; ks < 4; ks++) {
            const int cur = ks & 1;
            const int nxt = cur ^ 1;
            if (ks < 3) {
                const uint32_t kofs = (uint32_t)(ks + 1) * 32u;
                #pragma unroll
                for (int mt = 0; mt < 4; mt++)
                    LDSM4(afr[nxt][mt][0], afr[nxt][mt][1],
                          afr[nxt][mt][2], afr[nxt][mt][3],
                          st + SWZ128(a_base[mt] + kofs));
                #pragma unroll
                for (int np = 0; np < 4; np++)
                    LDSM4(bfr[nxt][2 * np][0], bfr[nxt][2 * np][1],
                          bfr[nxt][2 * np + 1][0], bfr[nxt][2 * np + 1][1],
                          bt + SWZ128(b_base[np] + kofs));
            }
            #pragma unroll
            for (int mt = 0; mt < 4; mt++)
                #pragma unroll
                for (int nt = 0; nt < 8; nt++)
                    MMA16816(acc[mt][nt], afr[cur][mt], bfr[cur][nt]);
        }
    }

    // ---------------- epilogue: regs -> gmem ------------------------------
    const size_t m_base = m0 + (size_t)wm * 64;
    const int    n_base = (int)n0 + wn * 64;
    const int r_off = lid >> 2;
    const int c_off = (lid & 3) * 2;
    #pragma unroll
    for (int mt = 0; mt < 4; mt++) {
        #pragma unroll
        for (int nt = 0; nt < 8; nt++) {
            size_t row = m_base + mt * 16 + r_off;
            int col = n_base + nt * 8 + c_off;
            float2 v0, v1;
            v0.x = acc[mt][nt][0];
            v0.y = acc[mt][nt][1];
            v1.x = acc[mt][nt][2];
            v1.y = acc[mt][nt][3];
            *reinterpret_cast<float2*>(&out[row * DO + col])       = v0;
            *reinterpret_cast<float2*>(&out[(row + 8) * DO + col]) = v1;
        }
    }
}

// ============================ launch ===================================
extern "C" void kernel_launch(void* const* d_in, const int* in_sizes, int n_in,
                              void* d_out, int out_size) {
    const float* x  = (const float*)d_in[0];   // [4,2048,4096]
    const float* wl = (const float*)d_in[1];   // [4096,4096]
    const float* ws = (const float*)d_in[2];   // [4096,1]
    const float* mk = (const float*)d_in[3];   // [1024,4096]
    const float* mv = (const float*)d_in[4];   // [1024,4096]
    float* out = (float*)d_out;                // [4,2048,4096] fp32

    // launch order keeps k_gemm in the ncu capture slot (4th launch).
    k_convert_x<<<(M_TOT * DI / 4 + 255) / 256, 256>>>(x);
    k_convert_w<<<(DO * DI / 4 + 255) / 256, 256>>>(wl, ws);
    k_scores<<<CAPM, 128>>>(mk, x);

    cudaFuncSetAttribute(k_gemm, cudaFuncAttributeMaxDynamicSharedMemorySize, GEMM_SMEM);
    k_gemm<<<64 * 16, 256, GEMM_SMEM>>>(out);

    k_softmax<<<1, 1024>>>();
    k_memout<<<DO / 128, 128>>>(mv);
    k_addmem<<<(M_TOT * DO / 4 + 255) / 256, 256>>>(out);
}

// round 9
// speedup vs baseline: 1.2620x; 1.2620x over previous
#include <cuda_runtime.h>
#include <cuda_fp16.h>
#include <cstdint>

// ============================ problem sizes ============================
#define M_TOT 8192      // B*S = 4*2048
#define DI    4096
#define DO    4096
#define CAPM  1024

// ============================ device scratch ===========================
__device__ __half g_x16[(size_t)M_TOT * DI];   // 64 MB fp16 activations
__device__ __half g_w16[(size_t)DO * DI];      // 32 MB fp16 dequantized weights
__device__ float  g_scores[CAPM];
__device__ float  g_memout[DO];

// ============================ PTX helpers ==============================
__device__ __forceinline__ uint32_t smem_u32(const void* p) {
    uint32_t a;
    asm("{ .reg .u64 t; cvta.to.shared.u64 t, %1; cvt.u32.u64 %0, t; }"
        : "=r"(a) : "l"(p));
    return a;
}

#define SWZ128(off) ((off) ^ (((off) >> 3) & 0x70))

#define CP16(dst, src) \
    asm volatile("cp.async.cg.shared.global [%0], [%1], 16;\n" \
                 :: "r"(dst), "l"(src) : "memory")
#define CP_COMMIT() asm volatile("cp.async.commit_group;\n" ::: "memory")
#define CP_WAIT(n)  asm volatile("cp.async.wait_group %0;\n" :: "n"(n) : "memory")

#define LDSM4(r0, r1, r2, r3, addr) \
    asm volatile("ldmatrix.sync.aligned.m8n8.x4.shared.b16 {%0,%1,%2,%3}, [%4];" \
                 : "=r"(r0), "=r"(r1), "=r"(r2), "=r"(r3) : "r"(addr))

#define MMA16816(c, a, b) \
    asm volatile("mma.sync.aligned.m16n8k16.row.col.f32.f16.f16.f32 " \
                 "{%0,%1,%2,%3}, {%4,%5,%6,%7}, {%8,%9}, {%0,%1,%2,%3};" \
                 : "+f"((c)[0]), "+f"((c)[1]), "+f"((c)[2]), "+f"((c)[3]) \
                 : "r"((a)[0]), "r"((a)[1]), "r"((a)[2]), "r"((a)[3]), \
                   "r"((b)[0]), "r"((b)[1]))

// ============================ prep kernels =============================
// convert x -> fp16, and blocks 0..CAPM-1 also compute one associative score
__global__ void k_convert_x(const float* __restrict__ x,
                            const float* __restrict__ keys) {
    int i = blockIdx.x * blockDim.x + threadIdx.x;          // float4 index
    const int n4 = (M_TOT * DI) / 4;
    if (i < n4) {
        float4 v = reinterpret_cast<const float4*>(x)[i];
        __half2 a = __floats2half2_rn(v.x, v.y);
        __half2 b = __floats2half2_rn(v.z, v.w);
        reinterpret_cast<__half2*>(g_x16)[2 * i]     = a;
        reinterpret_cast<__half2*>(g_x16)[2 * i + 1] = b;
    }
    if (blockIdx.x < CAPM) {
        int t = threadIdx.x;                                 // 256 threads
        const float4* kr = reinterpret_cast<const float4*>(keys + (size_t)blockIdx.x * DI);
        const float4* xr = reinterpret_cast<const float4*>(x);  // q = x[0, 0, :]
        float acc = 0.f;
        #pragma unroll
        for (int u = 0; u < 4; u++) {
            float4 a = kr[t + u * 256], b = xr[t + u * 256];
            acc += a.x * b.x + a.y * b.y + a.z * b.z + a.w * b.w;
        }
        #pragma unroll
        for (int o = 16; o > 0; o >>= 1) acc += __shfl_xor_sync(0xFFFFFFFFu, acc, o);
        __shared__ float red[8];
        if ((t & 31) == 0) red[t >> 5] = acc;
        __syncthreads();
        if (t == 0) {
            float s = 0.f;
            #pragma unroll
            for (int w = 0; w < 8; w++) s += red[w];
            g_scores[blockIdx.x] = s;
        }
    }
}

__global__ void k_convert_w(const float* __restrict__ wl, const float* __restrict__ ws) {
    int i = blockIdx.x * blockDim.x + threadIdx.x;          // float4 index
    const int n4 = (DO * DI) / 4;
    if (i < n4) {
        float4 v = reinterpret_cast<const float4*>(wl)[i];
        float s = ws[i >> 10];                              // row = i*4/4096
        __half2 a = __floats2half2_rn(v.x * s, v.y * s);
        __half2 b = __floats2half2_rn(v.z * s, v.w * s);
        reinterpret_cast<__half2*>(g_w16)[2 * i]     = a;
        reinterpret_cast<__half2*>(g_w16)[2 * i + 1] = b;
    }
}

// softmax (computed redundantly per block — trivial) + memory_out GEMV
__global__ void k_memsoft(const float* __restrict__ vals) {
    __shared__ float p[CAPM];
    __shared__ float red_m[4];
    __shared__ float red_s[4];
    int t = threadIdx.x;                                    // 128 threads
    float loc[8];
    float m = -1e30f;
    #pragma unroll
    for (int u = 0; u < 8; u++) {
        loc[u] = g_scores[t + u * 128];
        m = fmaxf(m, loc[u]);
    }
    #pragma unroll
    for (int o = 16; o > 0; o >>= 1) m = fmaxf(m, __shfl_xor_sync(0xFFFFFFFFu, m, o));
    if ((t & 31) == 0) red_m[t >> 5] = m;
    __syncthreads();
    m = fmaxf(fmaxf(red_m[0], red_m[1]), fmaxf(red_m[2], red_m[3]));
    float s = 0.f;
    #pragma unroll
    for (int u = 0; u < 8; u++) {
        loc[u] = expf(loc[u] - m);
        s += loc[u];
    }
    #pragma unroll
    for (int o = 16; o > 0; o >>= 1) s += __shfl_xor_sync(0xFFFFFFFFu, s, o);
    if ((t & 31) == 0) red_s[t >> 5] = s;
    __syncthreads();
    s = red_s[0] + red_s[1] + red_s[2] + red_s[3];
    float inv = 1.0f / s;
    #pragma unroll
    for (int u = 0; u < 8; u++) p[t + u * 128] = loc[u] * inv;
    __syncthreads();

    int o = blockIdx.x * 128 + t;                           // 32 blocks
    float acc = 0.f;
    #pragma unroll 4
    for (int j = 0; j < CAPM; j++) acc += p[j] * vals[(size_t)j * DO + o];
    g_memout[o] = acc;
}

// ============================ main GEMM ================================
// Legacy-tensor-core path (mma.sync / HMMA.16816) — tcgen05 unavailable under
// the harness's plain sm_103 PTX target.
// Occupancy-driven config (R7 profile: tensor=41.9%, occ=12.4% at 1 CTA/SM):
// CTA tile M=128, N=128, K-chunk=64; 256 threads = 8 warps (4Mx2N), warp 32x64.
// 3-stage cp.async pipeline, 32 KB/stage = 96 KB -> 2 CTAs/SM, 16 warps/SM.
// acc = 64 regs/thread; __launch_bounds__(256,2) keeps regs <= 128.
#define STAGES      3
#define NKI         64            // 4096 / 64
#define STAGE_BYTES 32768         // A 16 KB + B 16 KB
#define GEMM_SMEM   (STAGES * STAGE_BYTES)   // 98304

__device__ __forceinline__ void load_stage(uint32_t sb, int s, int kk,
                                           const __half* A, const __half* B,
                                           int tid) {
    uint32_t st = sb + s * STAGE_BYTES;
    uint32_t bt = st + 16384;
    size_t ko = (size_t)kk * 64;
    // A and B: each 128 rows x 128 B; thread does 4 chunks of each
    int r  = tid >> 1;
    int ch = (tid & 1) * 4;
    const char* ga = (const char*)(A + (size_t)r * DI + ko) + ch * 16;
    const char* gb = (const char*)(B + (size_t)r * DI + ko) + ch * 16;
    #pragma unroll
    for (int c = 0; c < 4; c++) {
        uint32_t off = (uint32_t)(r * 128 + (ch + c) * 16);
        CP16(st + SWZ128(off), ga + c * 16);
        CP16(bt + SWZ128(off), gb + c * 16);
    }
}

__global__ void __launch_bounds__(256, 2)
k_gemm(float* __restrict__ out) {
    extern __shared__ char smem[];
    uint32_t sb = smem_u32(smem);
    const int tid = threadIdx.x;
    const int wid = tid >> 5;
    const int lid = tid & 31;
    const int wm = wid & 3;          // 0..3  (M dimension, 32 rows each)
    const int wn = wid >> 2;         // 0..1  (N dimension, 64 cols each)

    // n varies fastest across blockIdx -> W slices stay hot in L2
    const size_t n0 = (size_t)(blockIdx.x & 31) * 128;   // 32 N tiles
    const size_t m0 = (size_t)(blockIdx.x >> 5) * 128;   // 64 M tiles
    const __half* Abase = g_x16 + m0 * DI;
    const __half* Bbase = g_w16 + n0 * DI;

    float acc[2][8][4];
    #pragma unroll
    for (int mt = 0; mt < 2; mt++)
        #pragma unroll
        for (int nt = 0; nt < 8; nt++)
            #pragma unroll
            for (int q = 0; q < 4; q++) acc[mt][nt][q] = 0.f;

    // per-lane UNSWIZZLED base offsets; swizzle applied on the full offset
    const uint32_t a_row  = (uint32_t)(wm * 32 + (lid & 15));
    const uint32_t a_colb = (uint32_t)((lid >> 4) * 16);
    const uint32_t b_row  = (uint32_t)(wn * 64 + (lid & 7) + ((lid >> 4) << 3));
    const uint32_t b_colb = (uint32_t)(((lid >> 3) & 1) * 16);

    uint32_t a_base[2], b_base[4];
    #pragma unroll
    for (int mt = 0; mt < 2; mt++)
        a_base[mt] = (a_row + mt * 16) * 128 + a_colb;
    #pragma unroll
    for (int np = 0; np < 4; np++)
        b_base[np] = (b_row + np * 16) * 128 + b_colb;

    // prologue: fill 2 of 3 stages
    load_stage(sb, 0, 0, Abase, Bbase, tid); CP_COMMIT();
    load_stage(sb, 1, 1, Abase, Bbase, tid); CP_COMMIT();

    int s_cur = 0, s_load = 2;
    for (int k = 0; k < NKI; k++) {
        CP_WAIT(1);                       // data for iter k landed
        __syncthreads();

        int kn = k + 2;
        if (kn < NKI) load_stage(sb, s_load, kn, Abase, Bbase, tid);
        CP_COMMIT();
        if (++s_load == STAGES) s_load = 0;

        uint32_t st = sb + s_cur * STAGE_BYTES;
        uint32_t bt = st + 16384;
        if (++s_cur == STAGES) s_cur = 0;

        #pragma unroll
        for (int ks = 0; ks < 4; ks++) {
            const uint32_t kofs = (uint32_t)ks * 32u;
            uint32_t a[2][4];
            uint32_t b[8][2];
            #pragma unroll
            for (int mt = 0; mt < 2; mt++)
                LDSM4(a[mt][0], a[mt][1], a[mt][2], a[mt][3],
                      st + SWZ128(a_base[mt] + kofs));
            #pragma unroll
            for (int np = 0; np < 4; np++)
                LDSM4(b[2 * np][0], b[2 * np][1],
                      b[2 * np + 1][0], b[2 * np + 1][1],
                      bt + SWZ128(b_base[np] + kofs));
            #pragma unroll
            for (int mt = 0; mt < 2; mt++)
                #pragma unroll
                for (int nt = 0; nt < 8; nt++)
                    MMA16816(acc[mt][nt], a[mt], b[nt]);
        }
    }

    // ------------- epilogue: regs -> gmem (+ 0.01 * memory_out) ----------
    const size_t m_base = m0 + (size_t)wm * 32;
    const int    n_base = (int)n0 + wn * 64;
    const int r_off = lid >> 2;
    const int c_off = (lid & 3) * 2;
    #pragma unroll
    for (int mt = 0; mt < 2; mt++) {
        #pragma unroll
        for (int nt = 0; nt < 8; nt++) {
            size_t row = m_base + mt * 16 + r_off;
            int col = n_base + nt * 8 + c_off;
            float2 mo = *reinterpret_cast<const float2*>(&g_memout[col]);
            float2 v0, v1;
            v0.x = acc[mt][nt][0] + 0.01f * mo.x;
            v0.y = acc[mt][nt][1] + 0.01f * mo.y;
            v1.x = acc[mt][nt][2] + 0.01f * mo.x;
            v1.y = acc[mt][nt][3] + 0.01f * mo.y;
            *reinterpret_cast<float2*>(&out[row * DO + col])       = v0;
            *reinterpret_cast<float2*>(&out[(row + 8) * DO + col]) = v1;
        }
    }
}

// ============================ launch ===================================
extern "C" void kernel_launch(void* const* d_in, const int* in_sizes, int n_in,
                              void* d_out, int out_size) {
    const float* x  = (const float*)d_in[0];   // [4,2048,4096]
    const float* wl = (const float*)d_in[1];   // [4096,4096]
    const float* ws = (const float*)d_in[2];   // [4096,1]
    const float* mk = (const float*)d_in[3];   // [1024,4096]
    const float* mv = (const float*)d_in[4];   // [1024,4096]
    float* out = (float*)d_out;                // [4,2048,4096] fp32

    // 4 launches; k_gemm stays in the ncu capture slot (4th launch).
    k_convert_x<<<(M_TOT * DI / 4 + 255) / 256, 256>>>(x, mk);
    k_convert_w<<<(DO * DI / 4 + 255) / 256, 256>>>(wl, ws);
    k_memsoft<<<DO / 128, 128>>>(mv);

    cudaFuncSetAttribute(k_gemm, cudaFuncAttributeMaxDynamicSharedMemorySize, GEMM_SMEM);
    k_gemm<<<64 * 32, 256, GEMM_SMEM>>>(out);
}